// round 1
// baseline (speedup 1.0000x reference)
#include <cuda_runtime.h>
#include <math.h>

#define BSZ    4
#define LEN    2048
#define DMODEL 1024
#define DINNER 2048
#define DHALF  1024
#define DSTATE 16
#define NROWS  (BSZ * LEN)   // 8192
#define XDBL_W 96

// ---------------- scratch (static device globals: allocation-free) ----------
__device__ __align__(16) float g_xz[(size_t)NROWS * DINNER];    // 64 MB
__device__ __align__(16) float g_u[(size_t)NROWS * DHALF];      // 32 MB  (silu(conv(xs)))
__device__ __align__(16) float g_ycat[(size_t)NROWS * DINNER];  // 64 MB  ([y | silu(conv(z))])
__device__ __align__(16) float g_xdbl[(size_t)NROWS * XDBL_W];  //  3 MB  (dt_low | B | C)
__device__ __align__(16) float g_delta[(size_t)NROWS * DHALF];  // 32 MB

// ---------------- generic 64x64x16 tiled fp32 GEMM --------------------------
// C[M,N] = A[M,K] @ B[K,N] (+bias). Row-major. M multiple of 64, K multiple
// of 16, N multiple of 4 (edge-guarded). 256 threads, 4x4 microtile.
__global__ void gemm64(const float* __restrict__ A, const float* __restrict__ B,
                       float* __restrict__ C, const float* __restrict__ bias,
                       int N, int K, int lda, int ldb, int ldc)
{
    __shared__ __align__(16) float As[16][64];
    __shared__ __align__(16) float Bs[16][64];

    const int tid   = threadIdx.x;
    const int brow0 = blockIdx.y * 64;
    const int bcol0 = blockIdx.x * 64;

    const int aRow = tid >> 2;          // 0..63
    const int aCol = (tid & 3) << 2;    // 0,4,8,12
    const int bRow = tid >> 4;          // 0..15
    const int bCol = (tid & 15) << 2;   // 0..60
    const int tm   = (tid >> 4) << 2;   // microtile row base
    const int tn   = (tid & 15) << 2;   // microtile col base

    float acc[4][4];
#pragma unroll
    for (int i = 0; i < 4; i++)
#pragma unroll
        for (int j = 0; j < 4; j++) acc[i][j] = 0.f;

    for (int k0 = 0; k0 < K; k0 += 16) {
        float4 av = *(const float4*)(A + (size_t)(brow0 + aRow) * lda + k0 + aCol);
        As[aCol + 0][aRow] = av.x;
        As[aCol + 1][aRow] = av.y;
        As[aCol + 2][aRow] = av.z;
        As[aCol + 3][aRow] = av.w;

        const int gcol = bcol0 + bCol;
        float4 bv = make_float4(0.f, 0.f, 0.f, 0.f);
        if (gcol < N)  // N % 4 == 0 and gcol % 4 == 0 -> whole float4 in range
            bv = *(const float4*)(B + (size_t)(k0 + bRow) * ldb + gcol);
        *(float4*)&Bs[bRow][bCol] = bv;

        __syncthreads();
#pragma unroll
        for (int kk = 0; kk < 16; kk++) {
            float4 a4 = *(const float4*)&As[kk][tm];
            float4 b4 = *(const float4*)&Bs[kk][tn];
            float ar[4] = {a4.x, a4.y, a4.z, a4.w};
            float br[4] = {b4.x, b4.y, b4.z, b4.w};
#pragma unroll
            for (int i = 0; i < 4; i++)
#pragma unroll
                for (int j = 0; j < 4; j++)
                    acc[i][j] = fmaf(ar[i], br[j], acc[i][j]);
        }
        __syncthreads();
    }

#pragma unroll
    for (int i = 0; i < 4; i++) {
        const int row = brow0 + tm + i;
#pragma unroll
        for (int j = 0; j < 4; j++) {
            const int col = bcol0 + tn + j;
            if (col < N) {
                float v = acc[i][j];
                if (bias) v += bias[col];
                C[(size_t)row * ldc + col] = v;
            }
        }
    }
}

// ---------------- depthwise conv (k=4, SAME: pad_l=1, pad_r=2) + SiLU -------
__global__ void conv_silu(const float* __restrict__ in, int istride,
                          const float* __restrict__ w, const float* __restrict__ bias,
                          float* __restrict__ out, int ostride)
{
    const int idx = blockIdx.x * blockDim.x + threadIdx.x;   // over NROWS*DHALF
    const int row = idx >> 10;        // b*LEN + l
    const int c   = idx & 1023;
    const int l   = row & (LEN - 1);

    float acc = bias[c];
#pragma unroll
    for (int j = 0; j < 4; j++) {
        const int ll = l - 1 + j;
        if ((unsigned)ll < (unsigned)LEN)
            acc = fmaf(w[j * DHALF + c], in[(size_t)(row - 1 + j) * istride + c], acc);
    }
    const float s = 1.f / (1.f + expf(-acc));
    out[(size_t)row * ostride + c] = acc * s;
}

// ---------------- delta = softplus(dtv + 2*inv_dt) (in place) ---------------
__global__ void softplus_k(float* __restrict__ dl, const float* __restrict__ inv_dt)
{
    const int idx = blockIdx.x * blockDim.x + threadIdx.x;   // over NROWS*DHALF
    const int c = idx & 1023;
    const float v = dl[idx] + 2.f * inv_dt[c];
    dl[idx] = (v > 20.f) ? v : log1pf(expf(v));
}

// ---------------- selective scan: thread per (b, d), 16 states in regs ------
// A[d][n] = -(n+1) => dA_n = e1^(n+1) with e1 = exp(-delta). One exp/step.
__global__ void scan_k(const float* __restrict__ u, const float* __restrict__ dl,
                       const float* __restrict__ xdbl, const float* __restrict__ Dv,
                       float* __restrict__ y)
{
    const int d = (blockIdx.x & 7) * 128 + threadIdx.x;   // 0..1023
    const int b = blockIdx.x >> 3;                        // 0..3
    const float Dd = Dv[d];

    float h[DSTATE];
#pragma unroll
    for (int n = 0; n < DSTATE; n++) h[n] = 0.f;

    size_t row = (size_t)b * LEN;
    for (int t = 0; t < LEN; t++, row++) {
        const float dval = dl[row * DHALF + d];
        const float uu   = u[row * DHALF + d];

        const float4* bc = (const float4*)(xdbl + row * XDBL_W + 64);
        float Bv[DSTATE], Cv[DSTATE];
        *(float4*)&Bv[0]  = __ldg(bc + 0);
        *(float4*)&Bv[4]  = __ldg(bc + 1);
        *(float4*)&Bv[8]  = __ldg(bc + 2);
        *(float4*)&Bv[12] = __ldg(bc + 3);
        *(float4*)&Cv[0]  = __ldg(bc + 4);
        *(float4*)&Cv[4]  = __ldg(bc + 5);
        *(float4*)&Cv[8]  = __ldg(bc + 6);
        *(float4*)&Cv[12] = __ldg(bc + 7);

        const float e1 = __expf(-dval);
        const float xd = dval * uu;
        float p = e1;
        float a0 = 0.f, a1 = 0.f, a2 = 0.f, a3 = 0.f;
#pragma unroll
        for (int n = 0; n < DSTATE; n++) {
            h[n] = fmaf(p, h[n], xd * Bv[n]);
            const float cy = h[n] * Cv[n];
            if ((n & 3) == 0)      a0 += cy;
            else if ((n & 3) == 1) a1 += cy;
            else if ((n & 3) == 2) a2 += cy;
            else                   a3 += cy;
            p *= e1;
        }
        y[row * DINNER + d] = (a0 + a1) + (a2 + a3) + uu * Dd;
    }
}

// ---------------- launch --------------------------------------------------
extern "C" void kernel_launch(void* const* d_in, const int* in_sizes, int n_in,
                              void* d_out, int out_size)
{
    const float* x       = (const float*)d_in[0];
    const float* W_in    = (const float*)d_in[1];
    const float* conv_xw = (const float*)d_in[2];
    const float* conv_xb = (const float*)d_in[3];
    const float* conv_zw = (const float*)d_in[4];
    const float* conv_zb = (const float*)d_in[5];
    const float* W_xdbl  = (const float*)d_in[6];
    const float* W_dt    = (const float*)d_in[7];
    const float* inv_dt  = (const float*)d_in[8];
    const float* Dvec    = (const float*)d_in[9];
    const float* W_out   = (const float*)d_in[10];
    const float* b_out   = (const float*)d_in[11];
    float* out = (float*)d_out;

    float *p_xz, *p_u, *p_ycat, *p_xdbl, *p_delta;
    cudaGetSymbolAddress((void**)&p_xz,    g_xz);
    cudaGetSymbolAddress((void**)&p_u,     g_u);
    cudaGetSymbolAddress((void**)&p_ycat,  g_ycat);
    cudaGetSymbolAddress((void**)&p_xdbl,  g_xdbl);
    cudaGetSymbolAddress((void**)&p_delta, g_delta);

    const int elemBlocks = (NROWS * DHALF) / 256;  // 32768

    // 1) xz = x @ W_in   (8192 x 2048 x 1024)
    gemm64<<<dim3(DINNER / 64, NROWS / 64), 256>>>(
        x, W_in, p_xz, nullptr, DINNER, DMODEL, DMODEL, DINNER, DINNER);

    // 2) u = silu(conv(xs));  3) ycat[:,1024:] = silu(conv(z))
    conv_silu<<<elemBlocks, 256>>>(p_xz,         DINNER, conv_xw, conv_xb, p_u,            DHALF);
    conv_silu<<<elemBlocks, 256>>>(p_xz + DHALF, DINNER, conv_zw, conv_zb, p_ycat + DHALF, DINNER);

    // 4) x_dbl = u @ W_xdbl   (8192 x 96 x 1024)
    gemm64<<<dim3((XDBL_W + 63) / 64, NROWS / 64), 256>>>(
        p_u, W_xdbl, p_xdbl, nullptr, XDBL_W, DHALF, DHALF, XDBL_W, XDBL_W);

    // 5) dtv = dt_low @ W_dt   (8192 x 1024 x 64), A = first 64 cols of x_dbl
    gemm64<<<dim3(DHALF / 64, NROWS / 64), 256>>>(
        p_xdbl, W_dt, p_delta, nullptr, DHALF, 64, XDBL_W, DHALF, DHALF);

    // 6) delta = softplus(dtv + 2*inv_dt)
    softplus_k<<<elemBlocks, 256>>>(p_delta, inv_dt);

    // 7) selective scan -> ycat[:, :1024]
    scan_k<<<32, 128>>>(p_u, p_delta, p_xdbl, Dvec, p_ycat);

    // 8) out = ycat @ W_out + b_out   (8192 x 1024 x 2048)
    gemm64<<<dim3(DMODEL / 64, NROWS / 64), 256>>>(
        p_ycat, W_out, out, b_out, DMODEL, DINNER, DINNER, DMODEL, DMODEL);
}

// round 3
// speedup vs baseline: 1.2884x; 1.2884x over previous
#include <cuda_runtime.h>
#include <math.h>

#define BSZ    4
#define LEN    2048
#define DMODEL 1024
#define DINNER 2048
#define DHALF  1024
#define DSTATE 16
#define NROWS  (BSZ * LEN)   // 8192
#define XDBL_W 96

// ---------------- scratch (static device globals: allocation-free) ----------
__device__ __align__(16) float g_xz[(size_t)NROWS * DINNER];    // 64 MB
__device__ __align__(16) float g_u[(size_t)NROWS * DHALF];      // 32 MB
__device__ __align__(16) float g_ycat[(size_t)NROWS * DINNER];  // 64 MB
__device__ __align__(16) float g_xdbl[(size_t)NROWS * XDBL_W];  //  3 MB
__device__ __align__(16) float g_delta[(size_t)NROWS * DHALF];  // 32 MB

// ================= tf32 tensor-core GEMM (fp32 accuracy via 3-term split) ===
// C[M,N] = A[M,K] @ B[K,N] (+bias). Row-major. M % 128 == 0, K % 16 == 0,
// N % 4 == 0 (edge-guarded per 64-wide tile). 256 threads.
// Block tile 128x64x16; 8 warps in 4(m) x 2(n); warp tile 32x32.
// STATIC shared memory only (29.7 KB) -> no cudaFuncSetAttribute needed.

__device__ __forceinline__ unsigned f2tf(float v) {
    unsigned r; asm("cvt.rna.tf32.f32 %0, %1;" : "=r"(r) : "f"(v)); return r;
}

__device__ __forceinline__ void mma8(float* c, const unsigned* a, unsigned b0, unsigned b1) {
    asm volatile(
        "mma.sync.aligned.m16n8k8.row.col.f32.tf32.tf32.f32 "
        "{%0,%1,%2,%3}, {%4,%5,%6,%7}, {%8,%9}, {%0,%1,%2,%3};\n"
        : "+f"(c[0]), "+f"(c[1]), "+f"(c[2]), "+f"(c[3])
        : "r"(a[0]), "r"(a[1]), "r"(a[2]), "r"(a[3]), "r"(b0), "r"(b1));
}

#define BM 128
#define BN 64
#define BK 16
#define AP 20        // A smem pitch: banks (20g+q) mod 32 all-distinct -> conflict-free
#define BP 72        // B smem pitch: banks (8q+g) mod 32 all-distinct -> conflict-free

__global__ __launch_bounds__(256)
void gemm_tc(const float* __restrict__ A, const float* __restrict__ B,
             float* __restrict__ C, const float* __restrict__ bias,
             int N, int K, int lda, int ldb, int ldc)
{
    __shared__ __align__(16) float sAh[BM * AP];   // 2560
    __shared__ __align__(16) float sAl[BM * AP];
    __shared__ __align__(16) float sBh[BK * BP];   // 1152
    __shared__ __align__(16) float sBl[BK * BP];

    const int tid  = threadIdx.x;
    const int lane = tid & 31;
    const int warp = tid >> 5;
    const int g = lane >> 2, q = lane & 3;
    const int wm = (warp & 3) * 32;
    const int wn = (warp >> 2) * 32;
    const int brow0 = blockIdx.y * BM;
    const int bcol0 = blockIdx.x * BN;

    // global load mapping
    const int a_r  = tid >> 2;          // 0..63 (rows a_r, a_r+64)
    const int a_c4 = (tid & 3) << 2;    // k offset 0,4,8,12
    const int b_r  = tid >> 4;          // 0..15
    const int b_c4 = tid & 15;          // col offset 4*b_c4

    const float* Aptr = A + (size_t)(brow0 + a_r) * lda + a_c4;
    const int bcol = bcol0 + b_c4 * 4;
    const bool bvalid = (bcol + 4) <= N;
    const float* Bptr = B + (size_t)b_r * ldb + bcol;

    float acc[8][4];
#pragma unroll
    for (int i = 0; i < 8; i++)
#pragma unroll
        for (int j = 0; j < 4; j++) acc[i][j] = 0.f;

    float4 apf[2], bpf;
#pragma unroll
    for (int i = 0; i < 2; i++) apf[i] = *(const float4*)(Aptr + (size_t)(64 * i) * lda);
    bpf = bvalid ? *(const float4*)Bptr : make_float4(0.f, 0.f, 0.f, 0.f);

    for (int k0 = 0; k0 < K; k0 += BK) {
        // ---- split + store staged chunk to smem ----
#pragma unroll
        for (int i = 0; i < 2; i++) {
            const float4 v = apf[i];
            const int off = (a_r + 64 * i) * AP + a_c4;
            float hx = __uint_as_float(f2tf(v.x));
            float hy = __uint_as_float(f2tf(v.y));
            float hz = __uint_as_float(f2tf(v.z));
            float hw = __uint_as_float(f2tf(v.w));
            *(float4*)&sAh[off] = make_float4(hx, hy, hz, hw);
            *(float4*)&sAl[off] = make_float4(
                __uint_as_float(f2tf(v.x - hx)), __uint_as_float(f2tf(v.y - hy)),
                __uint_as_float(f2tf(v.z - hz)), __uint_as_float(f2tf(v.w - hw)));
        }
        {
            const float4 v = bpf;
            const int off = b_r * BP + b_c4 * 4;
            float hx = __uint_as_float(f2tf(v.x));
            float hy = __uint_as_float(f2tf(v.y));
            float hz = __uint_as_float(f2tf(v.z));
            float hw = __uint_as_float(f2tf(v.w));
            *(float4*)&sBh[off] = make_float4(hx, hy, hz, hw);
            *(float4*)&sBl[off] = make_float4(
                __uint_as_float(f2tf(v.x - hx)), __uint_as_float(f2tf(v.y - hy)),
                __uint_as_float(f2tf(v.z - hz)), __uint_as_float(f2tf(v.w - hw)));
        }
        __syncthreads();

        // ---- prefetch next chunk while computing ----
        if (k0 + BK < K) {
            Aptr += BK;
            Bptr += (size_t)BK * ldb;
#pragma unroll
            for (int i = 0; i < 2; i++) apf[i] = *(const float4*)(Aptr + (size_t)(64 * i) * lda);
            bpf = bvalid ? *(const float4*)Bptr : make_float4(0.f, 0.f, 0.f, 0.f);
        }

        // ---- compute: 2 k8 steps ----
#pragma unroll
        for (int kk = 0; kk < BK; kk += 8) {
            unsigned ah[2][4], al[2][4], bh[4][2], bl[4][2];
#pragma unroll
            for (int m2 = 0; m2 < 2; m2++) {
                const int r0 = (wm + m2 * 16 + g) * AP + kk + q;
                const int r1 = r0 + 8 * AP;
                ah[m2][0] = __float_as_uint(sAh[r0]);
                ah[m2][1] = __float_as_uint(sAh[r1]);
                ah[m2][2] = __float_as_uint(sAh[r0 + 4]);
                ah[m2][3] = __float_as_uint(sAh[r1 + 4]);
                al[m2][0] = __float_as_uint(sAl[r0]);
                al[m2][1] = __float_as_uint(sAl[r1]);
                al[m2][2] = __float_as_uint(sAl[r0 + 4]);
                al[m2][3] = __float_as_uint(sAl[r1 + 4]);
            }
#pragma unroll
            for (int nn = 0; nn < 4; nn++) {
                const int c0 = (kk + q) * BP + wn + nn * 8 + g;
                bh[nn][0] = __float_as_uint(sBh[c0]);
                bh[nn][1] = __float_as_uint(sBh[c0 + 4 * BP]);
                bl[nn][0] = __float_as_uint(sBl[c0]);
                bl[nn][1] = __float_as_uint(sBl[c0 + 4 * BP]);
            }
#pragma unroll
            for (int m2 = 0; m2 < 2; m2++)
#pragma unroll
                for (int nn = 0; nn < 4; nn++) {
                    float* c = acc[m2 * 4 + nn];
                    mma8(c, ah[m2], bh[nn][0], bh[nn][1]);   // hi*hi
                    mma8(c, ah[m2], bl[nn][0], bl[nn][1]);   // hi*lo
                    mma8(c, al[m2], bh[nn][0], bh[nn][1]);   // lo*hi
                }
        }
        __syncthreads();
    }

    // ---- epilogue ----
#pragma unroll
    for (int m2 = 0; m2 < 2; m2++) {
        const int row0 = brow0 + wm + m2 * 16 + g;
#pragma unroll
        for (int nn = 0; nn < 4; nn++) {
            const int col = bcol0 + wn + nn * 8 + 2 * q;
            if (col < N) {
                const float* c = acc[m2 * 4 + nn];
                const float b0v = bias ? bias[col]     : 0.f;
                const float b1v = bias ? bias[col + 1] : 0.f;
                *(float2*)&C[(size_t)row0 * ldc + col] = make_float2(c[0] + b0v, c[1] + b1v);
                *(float2*)&C[(size_t)(row0 + 8) * ldc + col] = make_float2(c[2] + b0v, c[3] + b1v);
            }
        }
    }
}

// ---------------- depthwise conv (k=4, SAME: pad_l=1, pad_r=2) + SiLU -------
__global__ void conv_silu(const float* __restrict__ in, int istride,
                          const float* __restrict__ w, const float* __restrict__ bias,
                          float* __restrict__ out, int ostride)
{
    const int idx = blockIdx.x * blockDim.x + threadIdx.x;
    const int row = idx >> 10;
    const int c   = idx & 1023;
    const int l   = row & (LEN - 1);

    float acc = bias[c];
#pragma unroll
    for (int j = 0; j < 4; j++) {
        const int ll = l - 1 + j;
        if ((unsigned)ll < (unsigned)LEN)
            acc = fmaf(w[j * DHALF + c], in[(size_t)(row - 1 + j) * istride + c], acc);
    }
    const float s = 1.f / (1.f + expf(-acc));
    out[(size_t)row * ostride + c] = acc * s;
}

// ---------------- delta = softplus(dtv + 2*inv_dt) (in place) ---------------
__global__ void softplus_k(float* __restrict__ dl, const float* __restrict__ inv_dt)
{
    const int idx = blockIdx.x * blockDim.x + threadIdx.x;
    const int c = idx & 1023;
    const float v = dl[idx] + 2.f * inv_dt[c];
    dl[idx] = (v > 20.f) ? v : log1pf(expf(v));
}

// ---------------- selective scan: thread per (b, d), 16 states in regs ------
__global__ void scan_k(const float* __restrict__ u, const float* __restrict__ dl,
                       const float* __restrict__ xdbl, const float* __restrict__ Dv,
                       float* __restrict__ y)
{
    const int d = (blockIdx.x & 7) * 128 + threadIdx.x;
    const int b = blockIdx.x >> 3;
    const float Dd = Dv[d];

    float h[DSTATE];
#pragma unroll
    for (int n = 0; n < DSTATE; n++) h[n] = 0.f;

    size_t row = (size_t)b * LEN;
    for (int t = 0; t < LEN; t++, row++) {
        const float dval = dl[row * DHALF + d];
        const float uu   = u[row * DHALF + d];

        const float4* bc = (const float4*)(xdbl + row * XDBL_W + 64);
        float Bv[DSTATE], Cv[DSTATE];
        *(float4*)&Bv[0]  = __ldg(bc + 0);
        *(float4*)&Bv[4]  = __ldg(bc + 1);
        *(float4*)&Bv[8]  = __ldg(bc + 2);
        *(float4*)&Bv[12] = __ldg(bc + 3);
        *(float4*)&Cv[0]  = __ldg(bc + 4);
        *(float4*)&Cv[4]  = __ldg(bc + 5);
        *(float4*)&Cv[8]  = __ldg(bc + 6);
        *(float4*)&Cv[12] = __ldg(bc + 7);

        const float e1 = __expf(-dval);
        const float xd = dval * uu;

        // log-depth power tree: pw[i] = e1^(i+1), depth 4 instead of 15
        float pw[DSTATE];
        pw[0] = e1;
#pragma unroll
        for (int i = 1; i < DSTATE; i++) {
            const int a = (i - 1) >> 1;
            pw[i] = pw[a] * pw[i - 1 - a];
        }

        float a0 = 0.f, a1 = 0.f, a2 = 0.f, a3 = 0.f;
#pragma unroll
        for (int n = 0; n < DSTATE; n++) {
            h[n] = fmaf(pw[n], h[n], xd * Bv[n]);
            const float cy = h[n] * Cv[n];
            if ((n & 3) == 0)      a0 += cy;
            else if ((n & 3) == 1) a1 += cy;
            else if ((n & 3) == 2) a2 += cy;
            else                   a3 += cy;
        }
        y[row * DINNER + d] = (a0 + a1) + (a2 + a3) + uu * Dd;
    }
}

// ---------------- launch --------------------------------------------------
extern "C" void kernel_launch(void* const* d_in, const int* in_sizes, int n_in,
                              void* d_out, int out_size)
{
    const float* x       = (const float*)d_in[0];
    const float* W_in    = (const float*)d_in[1];
    const float* conv_xw = (const float*)d_in[2];
    const float* conv_xb = (const float*)d_in[3];
    const float* conv_zw = (const float*)d_in[4];
    const float* conv_zb = (const float*)d_in[5];
    const float* W_xdbl  = (const float*)d_in[6];
    const float* W_dt    = (const float*)d_in[7];
    const float* inv_dt  = (const float*)d_in[8];
    const float* Dvec    = (const float*)d_in[9];
    const float* W_out   = (const float*)d_in[10];
    const float* b_out   = (const float*)d_in[11];
    float* out = (float*)d_out;

    float *p_xz, *p_u, *p_ycat, *p_xdbl, *p_delta;
    cudaGetSymbolAddress((void**)&p_xz,    g_xz);
    cudaGetSymbolAddress((void**)&p_u,     g_u);
    cudaGetSymbolAddress((void**)&p_ycat,  g_ycat);
    cudaGetSymbolAddress((void**)&p_xdbl,  g_xdbl);
    cudaGetSymbolAddress((void**)&p_delta, g_delta);

    const int elemBlocks = (NROWS * DHALF) / 256;

    // 1) xz = x @ W_in   (8192 x 2048 x 1024)
    gemm_tc<<<dim3(DINNER / BN, NROWS / BM), 256>>>(
        x, W_in, p_xz, nullptr, DINNER, DMODEL, DMODEL, DINNER, DINNER);

    // 2) u = silu(conv(xs));  3) ycat[:,1024:] = silu(conv(z))
    conv_silu<<<elemBlocks, 256>>>(p_xz,         DINNER, conv_xw, conv_xb, p_u,            DHALF);
    conv_silu<<<elemBlocks, 256>>>(p_xz + DHALF, DINNER, conv_zw, conv_zb, p_ycat + DHALF, DINNER);

    // 4) x_dbl = u @ W_xdbl   (8192 x 96 x 1024)
    gemm_tc<<<dim3((XDBL_W + BN - 1) / BN, NROWS / BM), 256>>>(
        p_u, W_xdbl, p_xdbl, nullptr, XDBL_W, DHALF, DHALF, XDBL_W, XDBL_W);

    // 5) dtv = dt_low @ W_dt   (8192 x 1024 x 64)
    gemm_tc<<<dim3(DHALF / BN, NROWS / BM), 256>>>(
        p_xdbl, W_dt, p_delta, nullptr, DHALF, 64, XDBL_W, DHALF, DHALF);

    // 6) delta = softplus(dtv + 2*inv_dt)
    softplus_k<<<elemBlocks, 256>>>(p_delta, inv_dt);

    // 7) selective scan -> ycat[:, :1024]
    scan_k<<<32, 128>>>(p_u, p_delta, p_xdbl, Dvec, p_ycat);

    // 8) out = ycat @ W_out + b_out   (8192 x 1024 x 2048)
    gemm_tc<<<dim3(DMODEL / BN, NROWS / BM), 256>>>(
        p_ycat, W_out, out, b_out, DMODEL, DINNER, DINNER, DMODEL, DMODEL);
}

// round 4
// speedup vs baseline: 1.5594x; 1.2103x over previous
#include <cuda_runtime.h>
#include <cuda_bf16.h>
#include <math.h>

#define BSZ    4
#define LEN    2048
#define DMODEL 1024
#define DINNER 2048
#define DHALF  1024
#define DSTATE 16
#define NROWS  (BSZ * LEN)   // 8192
#define XDBL_W 96
#define DTRANK 64

// ---------------- scratch (static device globals: allocation-free) ----------
__device__ __align__(16) float g_xz[(size_t)NROWS * DINNER];    // 64 MB
__device__ __align__(16) float g_u[(size_t)NROWS * DHALF];      // 32 MB
__device__ __align__(16) float g_ycat[(size_t)NROWS * DINNER];  // 64 MB
__device__ __align__(16) float g_xdbl[(size_t)NROWS * XDBL_W];  //  3 MB
__device__ __align__(16) float g_delta[(size_t)NROWS * DHALF];  // 32 MB

// pre-split transposed weights: [N][K] bf16, hi + mid levels
__device__ __align__(16) __nv_bfloat16 g_Win_h[(size_t)DINNER * DMODEL];
__device__ __align__(16) __nv_bfloat16 g_Win_m[(size_t)DINNER * DMODEL];
__device__ __align__(16) __nv_bfloat16 g_Wxd_h[(size_t)XDBL_W * DHALF];
__device__ __align__(16) __nv_bfloat16 g_Wxd_m[(size_t)XDBL_W * DHALF];
__device__ __align__(16) __nv_bfloat16 g_Wdt_h[(size_t)DHALF * DTRANK];
__device__ __align__(16) __nv_bfloat16 g_Wdt_m[(size_t)DHALF * DTRANK];
__device__ __align__(16) __nv_bfloat16 g_Wout_h[(size_t)DMODEL * DINNER];
__device__ __align__(16) __nv_bfloat16 g_Wout_m[(size_t)DMODEL * DINNER];

// ---------------- weight transpose + bf16 hi/mid split ----------------------
// W[K][N] fp32 row-major  ->  Th/Tm[N][K] bf16. K, N multiples of 32.
__global__ void tsplit(const float* __restrict__ W, __nv_bfloat16* __restrict__ Th,
                       __nv_bfloat16* __restrict__ Tm, int K, int N)
{
    __shared__ float tile[32][33];
    const int n0 = blockIdx.x * 32, k0 = blockIdx.y * 32;
    const int tx = threadIdx.x, ty = threadIdx.y;   // 32 x 8
#pragma unroll
    for (int i = 0; i < 32; i += 8)
        tile[ty + i][tx] = W[(size_t)(k0 + ty + i) * N + n0 + tx];
    __syncthreads();
#pragma unroll
    for (int i = 0; i < 32; i += 8) {
        const float v = tile[tx][ty + i];           // W[k0+tx][n0+ty+i]
        const __nv_bfloat16 h = __float2bfloat16_rn(v);
        const __nv_bfloat16 m = __float2bfloat16_rn(v - __bfloat162float(h));
        const size_t o = (size_t)(n0 + ty + i) * K + k0 + tx;
        Th[o] = h;
        Tm[o] = m;
    }
}

// ================= bf16 3-term split GEMM on tensor cores ===================
// C[M,N] = A[M,K] @ B[K,N] (+bias), fp32 A, pre-split bf16 B^T ([N][K]).
// M % 128 == 0, K % 16 == 0. Block tile 128x128x16, 256 threads,
// 8 warps = 2(m) x 4(n), warp tile 64x32. Static smem 40 KB.

__device__ __forceinline__ void mma16(float* c, const unsigned* a, const unsigned* b) {
    asm volatile(
        "mma.sync.aligned.m16n8k16.row.col.f32.bf16.bf16.f32 "
        "{%0,%1,%2,%3}, {%4,%5,%6,%7}, {%8,%9}, {%0,%1,%2,%3};\n"
        : "+f"(c[0]), "+f"(c[1]), "+f"(c[2]), "+f"(c[3])
        : "r"(a[0]), "r"(a[1]), "r"(a[2]), "r"(a[3]), "r"(b[0]), "r"(b[1]));
}

__device__ __forceinline__ void split8(const float* v, unsigned* h4, unsigned* m4) {
#pragma unroll
    for (int i = 0; i < 4; i++) {
        const float x = v[2 * i], y = v[2 * i + 1];
        unsigned hp;
        asm("cvt.rn.satfinite.bf16x2.f32 %0, %1, %2;" : "=r"(hp) : "f"(y), "f"(x));
        const float hx = __uint_as_float(hp << 16);
        const float hy = __uint_as_float(hp & 0xffff0000u);
        const float rx = x - hx, ry = y - hy;
        unsigned mp;
        asm("cvt.rn.satfinite.bf16x2.f32 %0, %1, %2;" : "=r"(mp) : "f"(ry), "f"(rx));
        h4[i] = hp;
        m4[i] = mp;
    }
}

#define BM 128
#define BN 128
#define BK 16
#define PA 40    // bf16 pitch: word bank = 20*row + q -> conflict-free frag loads

__global__ __launch_bounds__(256)
void gemm_bf3(const float* __restrict__ A,
              const __nv_bfloat16* __restrict__ Bh,
              const __nv_bfloat16* __restrict__ Bm,
              float* __restrict__ C, const float* __restrict__ bias,
              int N, int K, int lda, int ldc)
{
    __shared__ __align__(16) __nv_bfloat16 sAh[BM * PA];   // 10240 B each
    __shared__ __align__(16) __nv_bfloat16 sAm[BM * PA];
    __shared__ __align__(16) __nv_bfloat16 sBh[BN * PA];
    __shared__ __align__(16) __nv_bfloat16 sBm[BN * PA];

    const int tid  = threadIdx.x;
    const int lane = tid & 31;
    const int warp = tid >> 5;
    const int g = lane >> 2, q = lane & 3;
    const int wm = (warp & 1) * 64;
    const int wn = (warp >> 1) * 32;
    const int brow0 = blockIdx.y * BM;
    const int bcol0 = blockIdx.x * BN;

    // A: thread -> (row ar, k-half akh*8 floats); B: (row br, k-half bkh*8 bf16)
    const int ar = tid >> 1, akh = tid & 1;
    const int br = tid >> 1, bkh = tid & 1;
    const float* Aptr = A + (size_t)(brow0 + ar) * lda + akh * 8;
    const int bn_g = bcol0 + br;
    const bool bvalid = bn_g < N;
    const __nv_bfloat16* Bhp = Bh + (size_t)bn_g * K + bkh * 8;
    const __nv_bfloat16* Bmp = Bm + (size_t)bn_g * K + bkh * 8;
    const int a_st = ar * PA + akh * 8;   // bf16 index
    const int b_st = br * PA + bkh * 8;

    float acc[16][4];
#pragma unroll
    for (int i = 0; i < 16; i++)
#pragma unroll
        for (int j = 0; j < 4; j++) acc[i][j] = 0.f;

    float4 a0 = *(const float4*)Aptr;
    float4 a1 = *(const float4*)(Aptr + 4);
    uint4 pbh = bvalid ? *(const uint4*)Bhp : make_uint4(0, 0, 0, 0);
    uint4 pbm = bvalid ? *(const uint4*)Bmp : make_uint4(0, 0, 0, 0);

    for (int k0 = 0; k0 < K; k0 += BK) {
        // ---- split A chunk + store staged data ----
        {
            float av[8] = {a0.x, a0.y, a0.z, a0.w, a1.x, a1.y, a1.z, a1.w};
            unsigned h4[4], m4[4];
            split8(av, h4, m4);
            *(uint4*)&sAh[a_st] = make_uint4(h4[0], h4[1], h4[2], h4[3]);
            *(uint4*)&sAm[a_st] = make_uint4(m4[0], m4[1], m4[2], m4[3]);
            *(uint4*)&sBh[b_st] = pbh;
            *(uint4*)&sBm[b_st] = pbm;
        }
        __syncthreads();

        // ---- prefetch next chunk ----
        if (k0 + BK < K) {
            Aptr += BK;
            Bhp  += BK;
            Bmp  += BK;
            a0 = *(const float4*)Aptr;
            a1 = *(const float4*)(Aptr + 4);
            pbh = bvalid ? *(const uint4*)Bhp : make_uint4(0, 0, 0, 0);
            pbm = bvalid ? *(const uint4*)Bmp : make_uint4(0, 0, 0, 0);
        }

        // ---- compute one m16n8k16 step over the warp tile ----
        unsigned bhf[4][2], bmf[4][2];
#pragma unroll
        for (int nn = 0; nn < 4; nn++) {
            const int n = (wn + nn * 8 + g) * PA + 2 * q;
            bhf[nn][0] = *(const unsigned*)&sBh[n];
            bhf[nn][1] = *(const unsigned*)&sBh[n + 8];
            bmf[nn][0] = *(const unsigned*)&sBm[n];
            bmf[nn][1] = *(const unsigned*)&sBm[n + 8];
        }
#pragma unroll
        for (int m2 = 0; m2 < 4; m2++) {
            const int r0 = (wm + m2 * 16 + g) * PA + 2 * q;
            const int r8 = r0 + 8 * PA;
            unsigned ah[4], am[4];
            ah[0] = *(const unsigned*)&sAh[r0];
            ah[1] = *(const unsigned*)&sAh[r8];
            ah[2] = *(const unsigned*)&sAh[r0 + 8];
            ah[3] = *(const unsigned*)&sAh[r8 + 8];
            am[0] = *(const unsigned*)&sAm[r0];
            am[1] = *(const unsigned*)&sAm[r8];
            am[2] = *(const unsigned*)&sAm[r0 + 8];
            am[3] = *(const unsigned*)&sAm[r8 + 8];
#pragma unroll
            for (int nn = 0; nn < 4; nn++) {
                float* c = acc[m2 * 4 + nn];
                mma16(c, ah, bhf[nn]);   // hi*hi
                mma16(c, ah, bmf[nn]);   // hi*mid
                mma16(c, am, bhf[nn]);   // mid*hi
            }
        }
        __syncthreads();
    }

    // ---- epilogue ----
#pragma unroll
    for (int m2 = 0; m2 < 4; m2++) {
        const int row0 = brow0 + wm + m2 * 16 + g;
#pragma unroll
        for (int nn = 0; nn < 4; nn++) {
            const int col = bcol0 + wn + nn * 8 + 2 * q;
            if (col < N) {
                const float* c = acc[m2 * 4 + nn];
                const float b0v = bias ? bias[col]     : 0.f;
                const float b1v = bias ? bias[col + 1] : 0.f;
                *(float2*)&C[(size_t)row0 * ldc + col] = make_float2(c[0] + b0v, c[1] + b1v);
                *(float2*)&C[(size_t)(row0 + 8) * ldc + col] = make_float2(c[2] + b0v, c[3] + b1v);
            }
        }
    }
}

// ---------------- depthwise conv (k=4, SAME: pad_l=1, pad_r=2) + SiLU -------
__global__ void conv_silu(const float* __restrict__ in, int istride,
                          const float* __restrict__ w, const float* __restrict__ bias,
                          float* __restrict__ out, int ostride)
{
    const int idx = blockIdx.x * blockDim.x + threadIdx.x;
    const int row = idx >> 10;
    const int c   = idx & 1023;
    const int l   = row & (LEN - 1);

    float acc = bias[c];
#pragma unroll
    for (int j = 0; j < 4; j++) {
        const int ll = l - 1 + j;
        if ((unsigned)ll < (unsigned)LEN)
            acc = fmaf(w[j * DHALF + c], in[(size_t)(row - 1 + j) * istride + c], acc);
    }
    const float s = 1.f / (1.f + expf(-acc));
    out[(size_t)row * ostride + c] = acc * s;
}

// ---------------- delta = softplus(dtv + 2*inv_dt) (in place) ---------------
__global__ void softplus_k(float* __restrict__ dl, const float* __restrict__ inv_dt)
{
    const int idx = blockIdx.x * blockDim.x + threadIdx.x;
    const int c = idx & 1023;
    const float v = dl[idx] + 2.f * inv_dt[c];
    dl[idx] = (v > 20.f) ? v : log1pf(expf(v));
}

// ---------------- selective scan: thread per (b, d), 16 states in regs ------
__global__ void scan_k(const float* __restrict__ u, const float* __restrict__ dl,
                       const float* __restrict__ xdbl, const float* __restrict__ Dv,
                       float* __restrict__ y)
{
    const int d = (blockIdx.x & 7) * 128 + threadIdx.x;
    const int b = blockIdx.x >> 3;
    const float Dd = Dv[d];

    float h[DSTATE];
#pragma unroll
    for (int n = 0; n < DSTATE; n++) h[n] = 0.f;

    size_t row = (size_t)b * LEN;
    for (int t = 0; t < LEN; t++, row++) {
        const float dval = dl[row * DHALF + d];
        const float uu   = u[row * DHALF + d];

        const float4* bc = (const float4*)(xdbl + row * XDBL_W + 64);
        float Bv[DSTATE], Cv[DSTATE];
        *(float4*)&Bv[0]  = __ldg(bc + 0);
        *(float4*)&Bv[4]  = __ldg(bc + 1);
        *(float4*)&Bv[8]  = __ldg(bc + 2);
        *(float4*)&Bv[12] = __ldg(bc + 3);
        *(float4*)&Cv[0]  = __ldg(bc + 4);
        *(float4*)&Cv[4]  = __ldg(bc + 5);
        *(float4*)&Cv[8]  = __ldg(bc + 6);
        *(float4*)&Cv[12] = __ldg(bc + 7);

        const float e1 = __expf(-dval);
        const float xd = dval * uu;

        float pw[DSTATE];
        pw[0] = e1;
#pragma unroll
        for (int i = 1; i < DSTATE; i++) {
            const int a = (i - 1) >> 1;
            pw[i] = pw[a] * pw[i - 1 - a];
        }

        float a0 = 0.f, a1 = 0.f, a2 = 0.f, a3 = 0.f;
#pragma unroll
        for (int n = 0; n < DSTATE; n++) {
            h[n] = fmaf(pw[n], h[n], xd * Bv[n]);
            const float cy = h[n] * Cv[n];
            if ((n & 3) == 0)      a0 += cy;
            else if ((n & 3) == 1) a1 += cy;
            else if ((n & 3) == 2) a2 += cy;
            else                   a3 += cy;
        }
        y[row * DINNER + d] = (a0 + a1) + (a2 + a3) + uu * Dd;
    }
}

// ---------------- launch --------------------------------------------------
extern "C" void kernel_launch(void* const* d_in, const int* in_sizes, int n_in,
                              void* d_out, int out_size)
{
    const float* x       = (const float*)d_in[0];
    const float* W_in    = (const float*)d_in[1];
    const float* conv_xw = (const float*)d_in[2];
    const float* conv_xb = (const float*)d_in[3];
    const float* conv_zw = (const float*)d_in[4];
    const float* conv_zb = (const float*)d_in[5];
    const float* W_xdbl  = (const float*)d_in[6];
    const float* W_dt    = (const float*)d_in[7];
    const float* inv_dt  = (const float*)d_in[8];
    const float* Dvec    = (const float*)d_in[9];
    const float* W_out   = (const float*)d_in[10];
    const float* b_out   = (const float*)d_in[11];
    float* out = (float*)d_out;

    float *p_xz, *p_u, *p_ycat, *p_xdbl, *p_delta;
    cudaGetSymbolAddress((void**)&p_xz,    g_xz);
    cudaGetSymbolAddress((void**)&p_u,     g_u);
    cudaGetSymbolAddress((void**)&p_ycat,  g_ycat);
    cudaGetSymbolAddress((void**)&p_xdbl,  g_xdbl);
    cudaGetSymbolAddress((void**)&p_delta, g_delta);

    __nv_bfloat16 *w_in_h, *w_in_m, *w_xd_h, *w_xd_m, *w_dt_h, *w_dt_m, *w_out_h, *w_out_m;
    cudaGetSymbolAddress((void**)&w_in_h,  g_Win_h);
    cudaGetSymbolAddress((void**)&w_in_m,  g_Win_m);
    cudaGetSymbolAddress((void**)&w_xd_h,  g_Wxd_h);
    cudaGetSymbolAddress((void**)&w_xd_m,  g_Wxd_m);
    cudaGetSymbolAddress((void**)&w_dt_h,  g_Wdt_h);
    cudaGetSymbolAddress((void**)&w_dt_m,  g_Wdt_m);
    cudaGetSymbolAddress((void**)&w_out_h, g_Wout_h);
    cudaGetSymbolAddress((void**)&w_out_m, g_Wout_m);

    const dim3 tsb(32, 8);

    // 0) pre-split + transpose all weight matrices to [N][K] bf16 hi/mid
    tsplit<<<dim3(DINNER / 32, DMODEL / 32), tsb>>>(W_in,   w_in_h,  w_in_m,  DMODEL, DINNER);
    tsplit<<<dim3(XDBL_W / 32, DHALF / 32),  tsb>>>(W_xdbl, w_xd_h,  w_xd_m,  DHALF,  XDBL_W);
    tsplit<<<dim3(DHALF / 32, DTRANK / 32),  tsb>>>(W_dt,   w_dt_h,  w_dt_m,  DTRANK, DHALF);
    tsplit<<<dim3(DMODEL / 32, DINNER / 32), tsb>>>(W_out,  w_out_h, w_out_m, DINNER, DMODEL);

    const int elemBlocks = (NROWS * DHALF) / 256;

    // 1) xz = x @ W_in   (8192 x 2048 x 1024)
    gemm_bf3<<<dim3(DINNER / BN, NROWS / BM), 256>>>(
        x, w_in_h, w_in_m, p_xz, nullptr, DINNER, DMODEL, DMODEL, DINNER);

    // 2) u = silu(conv(xs));  3) ycat[:,1024:] = silu(conv(z))
    conv_silu<<<elemBlocks, 256>>>(p_xz,         DINNER, conv_xw, conv_xb, p_u,            DHALF);
    conv_silu<<<elemBlocks, 256>>>(p_xz + DHALF, DINNER, conv_zw, conv_zb, p_ycat + DHALF, DINNER);

    // 4) x_dbl = u @ W_xdbl   (8192 x 96 x 1024)
    gemm_bf3<<<dim3(1, NROWS / BM), 256>>>(
        p_u, w_xd_h, w_xd_m, p_xdbl, nullptr, XDBL_W, DHALF, DHALF, XDBL_W);

    // 5) dtv = dt_low @ W_dt   (8192 x 1024 x 64)
    gemm_bf3<<<dim3(DHALF / BN, NROWS / BM), 256>>>(
        p_xdbl, w_dt_h, w_dt_m, p_delta, nullptr, DHALF, DTRANK, XDBL_W, DHALF);

    // 6) delta = softplus(dtv + 2*inv_dt)
    softplus_k<<<elemBlocks, 256>>>(p_delta, inv_dt);

    // 7) selective scan -> ycat[:, :1024]
    scan_k<<<32, 128>>>(p_u, p_delta, p_xdbl, Dvec, p_ycat);

    // 8) out = ycat @ W_out + b_out   (8192 x 1024 x 2048)
    gemm_bf3<<<dim3(DMODEL / BN, NROWS / BM), 256>>>(
        p_ycat, w_out_h, w_out_m, out, b_out, DMODEL, DINNER, DINNER, DMODEL);
}

// round 5
// speedup vs baseline: 1.8733x; 1.2013x over previous
#include <cuda_runtime.h>
#include <cuda_bf16.h>
#include <math.h>

#define BSZ    4
#define LEN    2048
#define DMODEL 1024
#define DINNER 2048
#define DHALF  1024
#define DSTATE 16
#define NROWS  (BSZ * LEN)   // 8192
#define XDBL_W 96
#define DTRANK 64

// ---------------- scratch (static device globals: allocation-free) ----------
__device__ __align__(16) float g_xz[(size_t)NROWS * DINNER];    // 64 MB
__device__ __align__(16) float g_u[(size_t)NROWS * DHALF];      // 32 MB
__device__ __align__(16) float g_ycat[(size_t)NROWS * DINNER];  // 64 MB
__device__ __align__(16) float g_xdbl[(size_t)NROWS * XDBL_W];  //  3 MB
__device__ __align__(16) float g_delta[(size_t)NROWS * DHALF];  // 32 MB

// pre-split transposed weights: [N][K] bf16, hi + mid levels
__device__ __align__(16) __nv_bfloat16 g_Win_h[(size_t)DINNER * DMODEL];
__device__ __align__(16) __nv_bfloat16 g_Win_m[(size_t)DINNER * DMODEL];
__device__ __align__(16) __nv_bfloat16 g_Wxd_h[(size_t)XDBL_W * DHALF];
__device__ __align__(16) __nv_bfloat16 g_Wxd_m[(size_t)XDBL_W * DHALF];
__device__ __align__(16) __nv_bfloat16 g_Wdt_h[(size_t)DHALF * DTRANK];
__device__ __align__(16) __nv_bfloat16 g_Wdt_m[(size_t)DHALF * DTRANK];
__device__ __align__(16) __nv_bfloat16 g_Wout_h[(size_t)DMODEL * DINNER];
__device__ __align__(16) __nv_bfloat16 g_Wout_m[(size_t)DMODEL * DINNER];

// ---------------- weight transpose + bf16 hi/mid split ----------------------
__global__ void tsplit(const float* __restrict__ W, __nv_bfloat16* __restrict__ Th,
                       __nv_bfloat16* __restrict__ Tm, int K, int N)
{
    __shared__ float tile[32][33];
    const int n0 = blockIdx.x * 32, k0 = blockIdx.y * 32;
    const int tx = threadIdx.x, ty = threadIdx.y;   // 32 x 8
#pragma unroll
    for (int i = 0; i < 32; i += 8)
        tile[ty + i][tx] = W[(size_t)(k0 + ty + i) * N + n0 + tx];
    __syncthreads();
#pragma unroll
    for (int i = 0; i < 32; i += 8) {
        const float v = tile[tx][ty + i];
        const __nv_bfloat16 h = __float2bfloat16_rn(v);
        const __nv_bfloat16 m = __float2bfloat16_rn(v - __bfloat162float(h));
        const size_t o = (size_t)(n0 + ty + i) * K + k0 + tx;
        Th[o] = h;
        Tm[o] = m;
    }
}

// ================= bf16 3-term split GEMM, ldmatrix fragments ===============
// C[M,N] = A[M,K] @ B[K,N], fp32 A, pre-split bf16 B^T ([N][K]).
// mode: 0 plain, 1 +bias, 2 softplus(acc + 2*bias).
// Block tile 128x128x16, 256 threads, 8 warps = 2(m) x 4(n), warp tile 64x32.

__device__ __forceinline__ void mma16(float* c, const unsigned* a, const unsigned* b) {
    asm volatile(
        "mma.sync.aligned.m16n8k16.row.col.f32.bf16.bf16.f32 "
        "{%0,%1,%2,%3}, {%4,%5,%6,%7}, {%8,%9}, {%0,%1,%2,%3};\n"
        : "+f"(c[0]), "+f"(c[1]), "+f"(c[2]), "+f"(c[3])
        : "r"(a[0]), "r"(a[1]), "r"(a[2]), "r"(a[3]), "r"(b[0]), "r"(b[1]));
}

__device__ __forceinline__ void ldsm4(unsigned* r, unsigned saddr) {
    asm volatile("ldmatrix.sync.aligned.m8n8.x4.shared.b16 {%0,%1,%2,%3}, [%4];"
        : "=r"(r[0]), "=r"(r[1]), "=r"(r[2]), "=r"(r[3]) : "r"(saddr));
}

__device__ __forceinline__ void split8(const float* v, unsigned* h4, unsigned* m4) {
#pragma unroll
    for (int i = 0; i < 4; i++) {
        const float x = v[2 * i], y = v[2 * i + 1];
        unsigned hp;
        asm("cvt.rn.satfinite.bf16x2.f32 %0, %1, %2;" : "=r"(hp) : "f"(y), "f"(x));
        const float hx = __uint_as_float(hp << 16);
        const float hy = __uint_as_float(hp & 0xffff0000u);
        const float rx = x - hx, ry = y - hy;
        unsigned mp;
        asm("cvt.rn.satfinite.bf16x2.f32 %0, %1, %2;" : "=r"(mp) : "f"(ry), "f"(rx));
        h4[i] = hp;
        m4[i] = mp;
    }
}

#define BM 128
#define BN 128
#define BK 16
#define PA 40    // bf16 pitch -> LDSM row starts cover all 32 banks

__global__ __launch_bounds__(256)
void gemm_bf3(const float* __restrict__ A,
              const __nv_bfloat16* __restrict__ Bh,
              const __nv_bfloat16* __restrict__ Bm,
              float* __restrict__ C, const float* __restrict__ bias,
              int N, int K, int lda, int ldc, int mode)
{
    __shared__ __align__(16) __nv_bfloat16 sAh[BM * PA];
    __shared__ __align__(16) __nv_bfloat16 sAm[BM * PA];
    __shared__ __align__(16) __nv_bfloat16 sBh[BN * PA];
    __shared__ __align__(16) __nv_bfloat16 sBm[BN * PA];

    const int tid  = threadIdx.x;
    const int lane = tid & 31;
    const int warp = tid >> 5;
    const int g = lane >> 2, q = lane & 3;
    const int wm = (warp & 1) * 64;
    const int wn = (warp >> 1) * 32;
    const int brow0 = blockIdx.y * BM;
    const int bcol0 = blockIdx.x * BN;

    const int ar = tid >> 1, akh = tid & 1;
    const float* Aptr = A + (size_t)(brow0 + ar) * lda + akh * 8;
    const int bn_g = bcol0 + ar;
    const bool bvalid = bn_g < N;
    const __nv_bfloat16* Bhp = Bh + (size_t)bn_g * K + akh * 8;
    const __nv_bfloat16* Bmp = Bm + (size_t)bn_g * K + akh * 8;
    const int a_st = ar * PA + akh * 8;

    // ldmatrix lane addresses (bytes into shared)
    const unsigned sAh_b = (unsigned)__cvta_generic_to_shared(sAh);
    const unsigned sAm_b = (unsigned)__cvta_generic_to_shared(sAm);
    const unsigned sBh_b = (unsigned)__cvta_generic_to_shared(sBh);
    const unsigned sBm_b = (unsigned)__cvta_generic_to_shared(sBm);
    const int a_lr = (lane & 7) + ((lane >> 3) & 1) * 8;   // row 0..15 in m16 tile
    const int a_lc = (lane >> 4) * 8;                      // k half
    const int b_lr = (lane & 7) + (lane >> 4) * 8;         // row 0..15 in n16 pair
    const int b_lc = ((lane >> 3) & 1) * 8;                // k half
    const unsigned aOffh = sAh_b + ((wm + a_lr) * PA + a_lc) * 2;
    const unsigned aOffm = sAm_b + ((wm + a_lr) * PA + a_lc) * 2;
    const unsigned bOffh = sBh_b + ((wn + b_lr) * PA + b_lc) * 2;
    const unsigned bOffm = sBm_b + ((wn + b_lr) * PA + b_lc) * 2;

    float acc[16][4];
#pragma unroll
    for (int i = 0; i < 16; i++)
#pragma unroll
        for (int j = 0; j < 4; j++) acc[i][j] = 0.f;

    float4 a0 = *(const float4*)Aptr;
    float4 a1 = *(const float4*)(Aptr + 4);
    uint4 pbh = bvalid ? *(const uint4*)Bhp : make_uint4(0, 0, 0, 0);
    uint4 pbm = bvalid ? *(const uint4*)Bmp : make_uint4(0, 0, 0, 0);

    for (int k0 = 0; k0 < K; k0 += BK) {
        {
            float av[8] = {a0.x, a0.y, a0.z, a0.w, a1.x, a1.y, a1.z, a1.w};
            unsigned h4[4], m4[4];
            split8(av, h4, m4);
            *(uint4*)&sAh[a_st] = make_uint4(h4[0], h4[1], h4[2], h4[3]);
            *(uint4*)&sAm[a_st] = make_uint4(m4[0], m4[1], m4[2], m4[3]);
            *(uint4*)&sBh[a_st] = pbh;
            *(uint4*)&sBm[a_st] = pbm;
        }
        __syncthreads();

        if (k0 + BK < K) {
            Aptr += BK;
            Bhp  += BK;
            Bmp  += BK;
            a0 = *(const float4*)Aptr;
            a1 = *(const float4*)(Aptr + 4);
            pbh = bvalid ? *(const uint4*)Bhp : make_uint4(0, 0, 0, 0);
            pbm = bvalid ? *(const uint4*)Bmp : make_uint4(0, 0, 0, 0);
        }

        // ---- fragments via ldmatrix, one m16n8k16 step ----
        unsigned bhf[2][4], bmf[2][4];
        ldsm4(bhf[0], bOffh);
        ldsm4(bhf[1], bOffh + 16 * PA * 2);
        ldsm4(bmf[0], bOffm);
        ldsm4(bmf[1], bOffm + 16 * PA * 2);
#pragma unroll
        for (int m2 = 0; m2 < 4; m2++) {
            unsigned ah[4], am[4];
            ldsm4(ah, aOffh + m2 * (16 * PA * 2));
            ldsm4(am, aOffm + m2 * (16 * PA * 2));
#pragma unroll
            for (int p = 0; p < 2; p++) {
                float* c0 = acc[m2 * 4 + 2 * p];
                float* c1 = acc[m2 * 4 + 2 * p + 1];
                mma16(c0, ah, &bhf[p][0]);
                mma16(c0, ah, &bmf[p][0]);
                mma16(c0, am, &bhf[p][0]);
                mma16(c1, ah, &bhf[p][2]);
                mma16(c1, ah, &bmf[p][2]);
                mma16(c1, am, &bhf[p][2]);
            }
        }
        __syncthreads();
    }

    // ---- epilogue ----
#pragma unroll
    for (int m2 = 0; m2 < 4; m2++) {
        const int row0 = brow0 + wm + m2 * 16 + g;
#pragma unroll
        for (int nn = 0; nn < 4; nn++) {
            const int col = bcol0 + wn + nn * 8 + 2 * q;
            if (col < N) {
                const float* c = acc[m2 * 4 + nn];
                float o0 = c[0], o1 = c[1], o2 = c[2], o3 = c[3];
                if (mode == 1) {
                    o0 += bias[col]; o2 += bias[col];
                    o1 += bias[col + 1]; o3 += bias[col + 1];
                } else if (mode == 2) {
                    const float i0 = 2.f * bias[col], i1 = 2.f * bias[col + 1];
                    o0 += i0; o2 += i0; o1 += i1; o3 += i1;
                    o0 = (o0 > 20.f) ? o0 : log1pf(expf(o0));
                    o1 = (o1 > 20.f) ? o1 : log1pf(expf(o1));
                    o2 = (o2 > 20.f) ? o2 : log1pf(expf(o2));
                    o3 = (o3 > 20.f) ? o3 : log1pf(expf(o3));
                }
                *(float2*)&C[(size_t)row0 * ldc + col] = make_float2(o0, o1);
                *(float2*)&C[(size_t)(row0 + 8) * ldc + col] = make_float2(o2, o3);
            }
        }
    }
}

// ---------------- depthwise conv (k=4, SAME: pad_l=1, pad_r=2) + SiLU -------
__global__ void conv_silu(const float* __restrict__ in, int istride,
                          const float* __restrict__ w, const float* __restrict__ bias,
                          float* __restrict__ out, int ostride)
{
    const int idx = blockIdx.x * blockDim.x + threadIdx.x;
    const int row = idx >> 10;
    const int c   = idx & 1023;
    const int l   = row & (LEN - 1);

    float acc = bias[c];
#pragma unroll
    for (int j = 0; j < 4; j++) {
        const int ll = l - 1 + j;
        if ((unsigned)ll < (unsigned)LEN)
            acc = fmaf(w[j * DHALF + c], in[(size_t)(row - 1 + j) * istride + c], acc);
    }
    const float s = 1.f / (1.f + expf(-acc));
    out[(size_t)row * ostride + c] = acc * s;
}

// ---------------- selective scan: 4 threads per (b,d), n-quad each ----------
__global__ void scan_k(const float* __restrict__ u, const float* __restrict__ dl,
                       const float* __restrict__ xdbl, const float* __restrict__ Dv,
                       float* __restrict__ y)
{
    const int tid = blockIdx.x * blockDim.x + threadIdx.x;  // 0..16383
    const int j  = tid & 3;          // n-quad: n = 4j..4j+3
    const int bd = tid >> 2;
    const int d  = bd & (DHALF - 1);
    const int b  = bd >> 10;
    const float Dd = Dv[d];

    float h0 = 0.f, h1 = 0.f, h2 = 0.f, h3 = 0.f;
    size_t row = (size_t)b * LEN;
    for (int t = 0; t < LEN; t++, row++) {
        const float dval = dl[row * DHALF + d];
        const float uu   = u[row * DHALF + d];
        const float4 Bq = __ldg((const float4*)(xdbl + row * XDBL_W + 64) + j);
        const float4 Cq = __ldg((const float4*)(xdbl + row * XDBL_W + 80) + j);

        const float e1 = __expf(-dval);
        const float e2 = e1 * e1, e4 = e2 * e2, e8 = e4 * e4;
        float pj = (j & 1) ? e4 : 1.f;
        if (j & 2) pj *= e8;
        const float p0 = pj * e1;
        const float p1 = p0 * e1, p2 = p1 * e1, p3 = p2 * e1;
        const float xd = dval * uu;

        h0 = fmaf(p0, h0, xd * Bq.x);
        h1 = fmaf(p1, h1, xd * Bq.y);
        h2 = fmaf(p2, h2, xd * Bq.z);
        h3 = fmaf(p3, h3, xd * Bq.w);

        float cy = fmaf(h0, Cq.x, h1 * Cq.y) + fmaf(h2, Cq.z, h3 * Cq.w);
        cy += __shfl_xor_sync(0xffffffffu, cy, 1);
        cy += __shfl_xor_sync(0xffffffffu, cy, 2);
        if (j == 0) y[row * DINNER + d] = cy + uu * Dd;
    }
}

// ---------------- launch --------------------------------------------------
extern "C" void kernel_launch(void* const* d_in, const int* in_sizes, int n_in,
                              void* d_out, int out_size)
{
    const float* x       = (const float*)d_in[0];
    const float* W_in    = (const float*)d_in[1];
    const float* conv_xw = (const float*)d_in[2];
    const float* conv_xb = (const float*)d_in[3];
    const float* conv_zw = (const float*)d_in[4];
    const float* conv_zb = (const float*)d_in[5];
    const float* W_xdbl  = (const float*)d_in[6];
    const float* W_dt    = (const float*)d_in[7];
    const float* inv_dt  = (const float*)d_in[8];
    const float* Dvec    = (const float*)d_in[9];
    const float* W_out   = (const float*)d_in[10];
    const float* b_out   = (const float*)d_in[11];
    float* out = (float*)d_out;

    float *p_xz, *p_u, *p_ycat, *p_xdbl, *p_delta;
    cudaGetSymbolAddress((void**)&p_xz,    g_xz);
    cudaGetSymbolAddress((void**)&p_u,     g_u);
    cudaGetSymbolAddress((void**)&p_ycat,  g_ycat);
    cudaGetSymbolAddress((void**)&p_xdbl,  g_xdbl);
    cudaGetSymbolAddress((void**)&p_delta, g_delta);

    __nv_bfloat16 *w_in_h, *w_in_m, *w_xd_h, *w_xd_m, *w_dt_h, *w_dt_m, *w_out_h, *w_out_m;
    cudaGetSymbolAddress((void**)&w_in_h,  g_Win_h);
    cudaGetSymbolAddress((void**)&w_in_m,  g_Win_m);
    cudaGetSymbolAddress((void**)&w_xd_h,  g_Wxd_h);
    cudaGetSymbolAddress((void**)&w_xd_m,  g_Wxd_m);
    cudaGetSymbolAddress((void**)&w_dt_h,  g_Wdt_h);
    cudaGetSymbolAddress((void**)&w_dt_m,  g_Wdt_m);
    cudaGetSymbolAddress((void**)&w_out_h, g_Wout_h);
    cudaGetSymbolAddress((void**)&w_out_m, g_Wout_m);

    const dim3 tsb(32, 8);

    // 0) pre-split + transpose all weight matrices to [N][K] bf16 hi/mid
    tsplit<<<dim3(DINNER / 32, DMODEL / 32), tsb>>>(W_in,   w_in_h,  w_in_m,  DMODEL, DINNER);
    tsplit<<<dim3(XDBL_W / 32, DHALF / 32),  tsb>>>(W_xdbl, w_xd_h,  w_xd_m,  DHALF,  XDBL_W);
    tsplit<<<dim3(DHALF / 32, DTRANK / 32),  tsb>>>(W_dt,   w_dt_h,  w_dt_m,  DTRANK, DHALF);
    tsplit<<<dim3(DMODEL / 32, DINNER / 32), tsb>>>(W_out,  w_out_h, w_out_m, DINNER, DMODEL);

    const int elemBlocks = (NROWS * DHALF) / 256;

    // 1) xz = x @ W_in   (8192 x 2048 x 1024)
    gemm_bf3<<<dim3(DINNER / BN, NROWS / BM), 256>>>(
        x, w_in_h, w_in_m, p_xz, nullptr, DINNER, DMODEL, DMODEL, DINNER, 0);

    // 2) u = silu(conv(xs));  3) ycat[:,1024:] = silu(conv(z))
    conv_silu<<<elemBlocks, 256>>>(p_xz,         DINNER, conv_xw, conv_xb, p_u,            DHALF);
    conv_silu<<<elemBlocks, 256>>>(p_xz + DHALF, DINNER, conv_zw, conv_zb, p_ycat + DHALF, DINNER);

    // 4) x_dbl = u @ W_xdbl   (8192 x 96 x 1024)
    gemm_bf3<<<dim3(1, NROWS / BM), 256>>>(
        p_u, w_xd_h, w_xd_m, p_xdbl, nullptr, XDBL_W, DHALF, DHALF, XDBL_W, 0);

    // 5) delta = softplus(dt_low @ W_dt + 2*inv_dt)   (fused epilogue)
    gemm_bf3<<<dim3(DHALF / BN, NROWS / BM), 256>>>(
        p_xdbl, w_dt_h, w_dt_m, p_delta, inv_dt, DHALF, DTRANK, XDBL_W, DHALF, 2);

    // 6) selective scan -> ycat[:, :1024]
    scan_k<<<64, 256>>>(p_u, p_delta, p_xdbl, Dvec, p_ycat);

    // 7) out = ycat @ W_out + b_out   (8192 x 1024 x 2048)
    gemm_bf3<<<dim3(DMODEL / BN, NROWS / BM), 256>>>(
        p_ycat, w_out_h, w_out_m, out, b_out, DMODEL, DINNER, DINNER, DMODEL, 1);
}